// round 3
// baseline (speedup 1.0000x reference)
#include <cuda_runtime.h>
#include <stdint.h>

#define BB 16
#define NN 2048
#define KK 20
#define ROWS (BB * NN)
#define LSTRIDE 256          // entries per row list (20 direct + up to 236 transpose)
#define TCAP 236

// ---- scratch (static __device__ — no allocations allowed) ----
// Per-row adjacency list: entry = (col << 32) | float_bits(v)
__device__ unsigned long long g_list[(size_t)ROWS * LSTRIDE];
__device__ int   g_tcnt[ROWS];   // transpose-append counters (zero-init; re-zeroed each call)
__device__ float g_dinv[ROWS];

// ---------------------------------------------------------------------------
// One block per row. Streams only A; noise fetched just for threshold
// survivors (doped > 1.8 requires relu(a) > 1.8 - 1e-4). Exact top-K via
// rank-count over survivors with jax's lowest-index tie-break
// (key = doped_bits<<11 | (2047-col)). Fallback to accept-all if < K survive.
__global__ __launch_bounds__(256) void k_topk(const float* __restrict__ A,
                                              const float* __restrict__ Noise) {
    const int row  = blockIdx.x;       // b * NN + i
    const int tid  = threadIdx.x;
    const int b    = row >> 11;
    const size_t base = (size_t)row << 11;

    __shared__ unsigned long long candK[NN];
    __shared__ uint32_t s_cnt, s_kslot;

    const float4* a4 = (const float4*)(A + base);

    float    rv[8];
    uint32_t db[8];
    bool     cand[8];
    int      cols[8];

    {
        float4 av  = a4[tid];
        float4 av2 = a4[256 + tid];
        float aa[8] = {av.x, av.y, av.z, av.w, av2.x, av2.y, av2.z, av2.w};
#pragma unroll
        for (int e = 0; e < 8; e++) {
            rv[e]   = fmaxf(aa[e], 0.0f);
            cols[e] = (e < 4) ? (tid * 4 + e) : (1024 + tid * 4 + (e - 4));
            cand[e] = false;
            db[e]   = 0u;
        }
    }

    if (tid == 0) { s_cnt = 0; s_kslot = 0; }
    __syncthreads();

    // ---- candidate pass: fetch noise only where relu could clear threshold
    const uint32_t THBITS = __float_as_uint(1.8f);
#pragma unroll
    for (int e = 0; e < 8; e++) {
        if (rv[e] > 1.79985f) {   // 1.8 - 1e-4 with margin
            float n = __ldg(Noise + base + cols[e]);
            float d = __fadd_rn(rv[e], __fmul_rn(n, 1e-4f));
            uint32_t dbits = __float_as_uint(d);
            if (dbits > THBITS) {
                cand[e] = true;
                db[e]   = dbits;
                uint32_t p = atomicAdd(&s_cnt, 1u);
                candK[p] = ((unsigned long long)dbits << 11)
                         | (unsigned long long)(2047 - cols[e]);
            }
        }
    }
    __syncthreads();
    uint32_t M = s_cnt;

    if (M < KK) {
        // ---- rare fallback: load full noise row, accept everything ----
        __syncthreads();
        if (tid == 0) s_cnt = 0;
        __syncthreads();
        const float4* n4 = (const float4*)(Noise + base);
        float4 nv  = n4[tid];
        float4 nv2 = n4[256 + tid];
        float no[8] = {nv.x, nv.y, nv.z, nv.w, nv2.x, nv2.y, nv2.z, nv2.w};
#pragma unroll
        for (int e = 0; e < 8; e++) {
            float d = __fadd_rn(rv[e], __fmul_rn(no[e], 1e-4f));
            db[e]   = __float_as_uint(d);
            cand[e] = true;
            uint32_t p = atomicAdd(&s_cnt, 1u);
            candK[p] = ((unsigned long long)db[e] << 11)
                     | (unsigned long long)(2047 - cols[e]);
        }
        __syncthreads();
        M = s_cnt;
    }

    // ---- exact rank-count; emit rank < K (exactly KK kept, keys distinct)
#pragma unroll
    for (int e = 0; e < 8; e++) {
        if (cand[e]) {
            const unsigned long long key =
                ((unsigned long long)db[e] << 11)
              | (unsigned long long)(2047 - cols[e]);
            uint32_t rank = 0;
            for (uint32_t q = 0; q < M; q++)
                rank += (candK[q] > key);
            if (rank < KK) {
                const unsigned long long entry =
                    ((unsigned long long)cols[e] << 32)
                  | (unsigned long long)__float_as_uint(rv[e]);
                // direct slot 0..19 in this row's list
                uint32_t p = atomicAdd(&s_kslot, 1u);
                g_list[(size_t)row * LSTRIDE + p] = entry;
                // transpose append into row (b, col)
                int jrow = b * NN + cols[e];
                uint32_t t = atomicAdd((unsigned int*)&g_tcnt[jrow], 1u);
                if (t < TCAP) {
                    g_list[(size_t)jrow * LSTRIDE + KK + t] =
                        ((unsigned long long)(row & 2047) << 32)
                      | (unsigned long long)__float_as_uint(rv[e]);
                }
            }
        }
    }
}

// ---------------------------------------------------------------------------
// Warp per row: d_i = 1 + 0.5 * sum of list values; g_dinv = rsqrt(d_i).
__global__ __launch_bounds__(256) void k_deg() {
    int warp = (blockIdx.x * 256 + threadIdx.x) >> 5;
    int lane = threadIdx.x & 31;
    if (warp >= ROWS) return;
    int tc = g_tcnt[warp]; if (tc > TCAP) tc = TCAP;
    int n  = KK + tc;
    float s = 0.0f;
    const unsigned long long* lst = g_list + (size_t)warp * LSTRIDE;
    for (int i = lane; i < n; i += 32)
        s += __uint_as_float((uint32_t)lst[i]);
#pragma unroll
    for (int off = 16; off; off >>= 1)
        s += __shfl_down_sync(0xffffffffu, s, off);
    if (lane == 0)
        g_dinv[warp] = rsqrtf(fmaf(0.5f, s, 1.0f));
}

// ---------------------------------------------------------------------------
// Block per row: zero smem row buffer, scatter weighted entries + diagonal,
// stream the dense row to global with float4 stores (covers every output).
__global__ __launch_bounds__(256) void k_writer(float* __restrict__ out) {
    const int row = blockIdx.x;
    const int tid = threadIdx.x;
    const int b   = row >> 11;

    __shared__ float srow[NN];
    float4* s4 = (float4*)srow;
    s4[tid]       = make_float4(0.f, 0.f, 0.f, 0.f);
    s4[256 + tid] = make_float4(0.f, 0.f, 0.f, 0.f);

    const float di = g_dinv[row];
    int tc = g_tcnt[row]; if (tc > TCAP) tc = TCAP;
    const int n = KK + tc;
    __syncthreads();

    const unsigned long long* lst = g_list + (size_t)row * LSTRIDE;
    for (int t = tid; t < n; t += 256) {
        unsigned long long e = lst[t];
        int   col = (int)(e >> 32);
        float v   = __uint_as_float((uint32_t)e);
        float w   = 0.5f * v * di * g_dinv[b * NN + col];
        atomicAdd(&srow[col], w);
    }
    if (tid == 0) atomicAdd(&srow[row & 2047], di * di);
    __syncthreads();

    float4* o4 = (float4*)(out + ((size_t)row << 11));
    o4[tid]       = s4[tid];
    o4[256 + tid] = s4[256 + tid];
}

// ---------------------------------------------------------------------------
extern "C" void kernel_launch(void* const* d_in, const int* in_sizes, int n_in,
                              void* d_out, int out_size) {
    const float* A     = (const float*)d_in[0];
    const float* Noise = (const float*)d_in[1];
    float* out = (float*)d_out;

    k_topk  <<<ROWS, 256>>>(A, Noise);
    k_deg   <<<(ROWS * 32 + 255) / 256, 256>>>();
    k_writer<<<ROWS, 256>>>(out);

    // re-zero transpose counters for the next call (zero-init at load keeps
    // the "zero on entry" invariant for every call, including the first)
    void* tcnt_ptr = nullptr;
    cudaGetSymbolAddress(&tcnt_ptr, g_tcnt);
    cudaMemsetAsync(tcnt_ptr, 0, ROWS * sizeof(int));
}

// round 4
// speedup vs baseline: 3.2364x; 3.2364x over previous
#include <cuda_runtime.h>
#include <stdint.h>

#define BB 16
#define NN 2048
#define KK 20
#define ROWS (BB * NN)
#define LSTRIDE 512          // entries per row list (20 direct + up to TCAP transpose)
#define TCAP (LSTRIDE - KK)

// ---- scratch (static __device__ — no allocations allowed) ----
// Per-row adjacency list entry = (col << 32) | float_bits(v)
__device__ unsigned long long g_list[(size_t)ROWS * LSTRIDE];
__device__ int   g_tcnt[ROWS];   // transpose counters (zero-init; re-zeroed at end of call)
__device__ float g_dinv[ROWS];

// ---------------------------------------------------------------------------
// One block per row. Streams only A; noise fetched only for elements whose
// relu could clear the 1.8 doped threshold. Exact top-K via rank-count over
// candidates with jax's lowest-index tie-break (key = doped_bits<<11 |
// (2047-col)); accept-all fallback (full 2048-capacity smem) if < K survive.
__global__ __launch_bounds__(256) void k_topk(const float* __restrict__ A,
                                              const float* __restrict__ Noise) {
    const int row  = blockIdx.x;       // b * NN + i
    const int tid  = threadIdx.x;
    const int b    = row >> 11;
    const size_t base = (size_t)row << 11;

    __shared__ unsigned long long candK[NN];  // full capacity: no overflow logic
    __shared__ float    candR[NN];
    __shared__ uint32_t s_cnt, s_kslot;

    const float4* a4 = (const float4*)(A + base);
    float4 av  = a4[tid];
    float4 av2 = a4[256 + tid];
    float aa[8] = {av.x, av.y, av.z, av.w, av2.x, av2.y, av2.z, av2.w};

    if (tid == 0) { s_cnt = 0; s_kslot = 0; }
    __syncthreads();

    // ---- fast candidate pass: doped>1.8 requires a > 1.8-1e-4 ----
    const uint32_t THBITS = __float_as_uint(1.8f);
#pragma unroll
    for (int e = 0; e < 8; e++) {
        if (aa[e] > 1.79985f) {
            int col = (e < 4) ? (tid * 4 + e) : (1024 + tid * 4 + (e - 4));
            float n = __ldg(Noise + base + col);
            float d = __fadd_rn(aa[e], __fmul_rn(n, 1e-4f));
            uint32_t dbits = __float_as_uint(d);
            if (dbits > THBITS) {
                uint32_t p = atomicAdd(&s_cnt, 1u);
                candK[p] = ((unsigned long long)dbits << 11)
                         | (unsigned long long)(2047 - col);
                candR[p] = aa[e];
            }
        }
    }
    __syncthreads();
    uint32_t M = s_cnt;

    if (M < KK) {
        // ---- rare fallback: full noise row, accept every element ----
        __syncthreads();
        if (tid == 0) s_cnt = 0;
        __syncthreads();
        const float4* n4 = (const float4*)(Noise + base);
        float4 nv  = n4[tid];
        float4 nv2 = n4[256 + tid];
        float no[8] = {nv.x, nv.y, nv.z, nv.w, nv2.x, nv2.y, nv2.z, nv2.w};
#pragma unroll
        for (int e = 0; e < 8; e++) {
            float r = fmaxf(aa[e], 0.0f);
            float d = __fadd_rn(r, __fmul_rn(no[e], 1e-4f));
            int col = (e < 4) ? (tid * 4 + e) : (1024 + tid * 4 + (e - 4));
            uint32_t p = atomicAdd(&s_cnt, 1u);
            candK[p] = ((unsigned long long)__float_as_uint(d) << 11)
                     | (unsigned long long)(2047 - col);
            candR[p] = r;
        }
        __syncthreads();
        M = s_cnt;
    }

    // ---- parallel rank-count: candidate i handled by thread (i mod 256) ----
    for (uint32_t i = tid; i < M; i += 256) {
        const unsigned long long key = candK[i];
        uint32_t rank = 0;
        for (uint32_t q = 0; q < M; q++)
            rank += (candK[q] > key);          // smem broadcast reads
        if (rank < KK) {
            int   col = 2047 - (int)(key & 2047u);
            float r   = candR[i];
            unsigned long long entry =
                ((unsigned long long)col << 32)
              | (unsigned long long)__float_as_uint(r);
            uint32_t p = atomicAdd(&s_kslot, 1u);
            g_list[(size_t)row * LSTRIDE + p] = entry;          // direct slot
            int jrow = b * NN + col;                            // transpose
            uint32_t t = atomicAdd((unsigned int*)&g_tcnt[jrow], 1u);
            if (t < TCAP)
                g_list[(size_t)jrow * LSTRIDE + KK + t] =
                    ((unsigned long long)(row & 2047) << 32)
                  | (unsigned long long)__float_as_uint(r);
        }
    }
}

// ---------------------------------------------------------------------------
// Warp per row: d_i = 1 + 0.5 * (sum of list values); self-loops appear in
// both direct and transpose entries, matching rowsum+colsum double-count.
__global__ __launch_bounds__(256) void k_deg() {
    int warp = (blockIdx.x * 256 + threadIdx.x) >> 5;
    int lane = threadIdx.x & 31;
    if (warp >= ROWS) return;
    int tc = g_tcnt[warp]; if (tc > TCAP) tc = TCAP;
    int n  = KK + tc;
    float s = 0.0f;
    const unsigned long long* lst = g_list + (size_t)warp * LSTRIDE;
    for (int i = lane; i < n; i += 32)
        s += __uint_as_float((uint32_t)lst[i]);
#pragma unroll
    for (int off = 16; off; off >>= 1)
        s += __shfl_down_sync(0xffffffffu, s, off);
    if (lane == 0)
        g_dinv[warp] = rsqrtf(fmaf(0.5f, s, 1.0f));
}

// ---------------------------------------------------------------------------
// Block per row: zero smem row, scatter weighted list entries + diagonal,
// stream dense row out with float4 stores (covers every output element).
__global__ __launch_bounds__(256) void k_writer(float* __restrict__ out) {
    const int row = blockIdx.x;
    const int tid = threadIdx.x;
    const int b   = row >> 11;

    __shared__ float srow[NN];
    float4* s4 = (float4*)srow;
    s4[tid]       = make_float4(0.f, 0.f, 0.f, 0.f);
    s4[256 + tid] = make_float4(0.f, 0.f, 0.f, 0.f);

    const float di = g_dinv[row];
    int tc = g_tcnt[row]; if (tc > TCAP) tc = TCAP;
    const int n = KK + tc;
    __syncthreads();

    const unsigned long long* lst = g_list + (size_t)row * LSTRIDE;
    for (int t = tid; t < n; t += 256) {
        unsigned long long e = lst[t];
        int   col = (int)(e >> 32);
        float v   = __uint_as_float((uint32_t)e);
        float w   = 0.5f * v * di * g_dinv[b * NN + col];
        atomicAdd(&srow[col], w);
    }
    if (tid == 0) atomicAdd(&srow[row & 2047], di * di);
    __syncthreads();

    float4* o4 = (float4*)(out + ((size_t)row << 11));
    o4[tid]       = s4[tid];
    o4[256 + tid] = s4[256 + tid];
}

// ---------------------------------------------------------------------------
// Re-zero transpose counters (runs last; static zero-init covers first call).
__global__ void k_zero() {
    int i = blockIdx.x * blockDim.x + threadIdx.x;
    if (i < ROWS) g_tcnt[i] = 0;
}

// ---------------------------------------------------------------------------
extern "C" void kernel_launch(void* const* d_in, const int* in_sizes, int n_in,
                              void* d_out, int out_size) {
    const float* A     = (const float*)d_in[0];
    const float* Noise = (const float*)d_in[1];
    float* out = (float*)d_out;

    k_topk  <<<ROWS, 256>>>(A, Noise);
    k_deg   <<<(ROWS * 32 + 255) / 256, 256>>>();
    k_writer<<<ROWS, 256>>>(out);
    k_zero  <<<(ROWS + 255) / 256, 256>>>();
}